// round 7
// baseline (speedup 1.0000x reference)
#include <cuda_runtime.h>
#include <math.h>

#define BN_ 1344
#define L_ 2048
#define PNUM_ 255
#define D_ 128
#define PRED_ 96
#define ROWS_ (BN_*PNUM_)      /* 342720 = 64*5355 */
#define KHEAD_ (D_*PNUM_)      /* 32640 */
#define EPS_ 1e-5f
#define EMASCALE_ 0.7071067811865476f
#define SWR(c) ((((c)>>3)&3)*8)

__device__ float g_bufA[ROWS_*D_];
__device__ float g_bufB[ROWS_*D_];
__device__ float g_u[(size_t)BN_*KHEAD_];
__device__ float g_ema[D_*4];

__device__ __forceinline__ float2 ffma2(float2 a, float2 b, float2 c) {
    unsigned long long au = *reinterpret_cast<unsigned long long*>(&a);
    unsigned long long bu = *reinterpret_cast<unsigned long long*>(&b);
    unsigned long long cu = *reinterpret_cast<unsigned long long*>(&c);
    unsigned long long ru;
    asm("fma.rn.f32x2 %0, %1, %2, %3;" : "=l"(ru) : "l"(au), "l"(bu), "l"(cu));
    return *reinterpret_cast<float2*>(&ru);
}
__device__ __forceinline__ float2 dupp(float v){
    unsigned long long ru;
    asm("mov.b64 %0, {%1, %1};" : "=l"(ru) : "f"(v));
    return *reinterpret_cast<float2*>(&ru);
}
__device__ __forceinline__ float2 dup2(float v){ return make_float2(v,v); }
__device__ __forceinline__ float2 lo2(float4 v){ return make_float2(v.x,v.y); }
__device__ __forceinline__ float2 hi2(float4 v){ return make_float2(v.z,v.w); }

// ============ K0: EMA coefficients ============
__global__ void k0_emaparam(const float* __restrict__ delta, const float* __restrict__ alpha,
                            const float* __restrict__ beta, const float* __restrict__ gamma)
{
    int d = threadIdx.x;
    if (d < D_) {
        #pragma unroll
        for (int n = 0; n < 2; n++) {
            int i = d*2 + n;
            float p = 1.f/(1.f + expf(-delta[i]));
            float q = 1.f - p * (1.f/(1.f + expf(-alpha[i])));
            float a = p * beta[i] * gamma[i] * EMASCALE_;
            g_ema[d*4 + n*2 + 0] = q;
            g_ema[d*4 + n*2 + 1] = a;
        }
    }
}

// ============ K1: featproj LEMblock 16->256->128, 64-row tiles ============
// smem: w1p f4[16*64] permuted, wrs f4[16*32], w2s f4[256*32] natural,
//       xs1 f[16*64], hs f[256*64], part f2[64*4]
#define SM1_BYTES (16*64*16 + 16*32*16 + 256*32*16 + 16*64*4 + 256*64*4 + 64*4*8)

__global__ __launch_bounds__(256, 1)
void k1_featproj(const float* __restrict__ x,
                 const float* __restrict__ w1, const float* __restrict__ b1,
                 const float* __restrict__ w2, const float* __restrict__ b2,
                 const float* __restrict__ wr, const float* __restrict__ br,
                 const float* __restrict__ g,  const float* __restrict__ be)
{
    extern __shared__ unsigned char smraw[];
    float4* w1p = (float4*)smraw;              // [16][64] permuted: k*64 + wc*16 + jq*4 + cg
    float4* wrs = w1p + 16*64;                 // [16][32] natural
    float4* w2s = wrs + 16*32;                 // [256][32] natural
    float*  xs1 = (float*)(w2s + 256*32);      // [16][64]
    float*  hs  = xs1 + 16*64;                 // [256][64]
    float2* part = (float2*)(hs + 256*64);     // [64][4]

    int tid = threadIdx.x;
    const float4* w1g = (const float4*)w1;
    const float4* wrg = (const float4*)wr;
    const float4* w2g = (const float4*)w2;
    for (int i = tid; i < 16*64; i += 256) {
        int k = i >> 6, s = i & 63;
        int wcq = s >> 4, rem = s & 15, jq = rem >> 2, cgq = rem & 3;
        w1p[i] = w1g[k*64 + wcq*16 + cgq*4 + jq];
    }
    for (int i = tid; i < 16*32; i += 256)  wrs[i] = wrg[i];
    for (int i = tid; i < 256*32; i += 256) w2s[i] = w2g[i];

    int wid = tid >> 5, lane = tid & 31;
    int wrow = wid & 1, wc = wid >> 1;         // 2 x 4 warp grid
    int rg = lane >> 2, cg = lane & 3;
    int r0 = wrow*32 + rg*4;                   // 4 rows
    int c0 = wc*32 + cg*8;                     // 8 cols (residual/B/LN)
    int cA0 = wc*64 + cg*16;                   // 16 cols (phase A)
    int f0 = wc*8 + cg*2;                      // float4 idx base for 8-col tiles

    // persistent biases
    float2 bhA[8], by[4];
    #pragma unroll
    for (int j = 0; j < 8; j++) bhA[j] = *(const float2*)(b1 + cA0 + 2*j);
    #pragma unroll
    for (int j = 0; j < 4; j++) {
        float2 a = *(const float2*)(b2 + c0 + 2*j);
        float2 b = *(const float2*)(br + c0 + 2*j);
        by[j] = make_float2(a.x + b.x, a.y + b.y);
    }
    __syncthreads();

    const int NTILES = ROWS_/64;               // 5355
    for (int tile = blockIdx.x; tile < NTILES; tile += gridDim.x) {
        int row0 = tile*64;
        __syncthreads();                       // protect xs1/part reuse
        {   // patch gather -> xs1[c][r]
            int r = tid >> 2, q = (tid & 3)*4;
            int grow = row0 + r;
            int bn = grow/255, p = grow - bn*255;
            float4 v = *(const float4*)(x + bn*L_ + p*8 + q);
            xs1[(q+0)*64 + r] = v.x;
            xs1[(q+1)*64 + r] = v.y;
            xs1[(q+2)*64 + r] = v.z;
            xs1[(q+3)*64 + r] = v.w;
        }
        __syncthreads();

        // phase A: ah[4rows][8 colpairs] = x @ w1 + b1  (cols cA0..cA0+15)
        float2 ah[4][8];
        #pragma unroll
        for (int i = 0; i < 4; i++)
            #pragma unroll
            for (int j = 0; j < 8; j++) ah[i][j] = bhA[j];
        #pragma unroll
        for (int k = 0; k < 16; k++) {
            float4 xv = *(const float4*)(xs1 + k*64 + r0);
            float2 xd0 = dupp(xv.x), xd1 = dupp(xv.y), xd2 = dupp(xv.z), xd3 = dupp(xv.w);
            #pragma unroll
            for (int jq = 0; jq < 4; jq++) {
                float4 wv = w1p[k*64 + wc*16 + jq*4 + cg];
                float2 wl = lo2(wv), wh = hi2(wv);
                ah[0][2*jq]   = ffma2(xd0, wl, ah[0][2*jq]);
                ah[1][2*jq]   = ffma2(xd1, wl, ah[1][2*jq]);
                ah[2][2*jq]   = ffma2(xd2, wl, ah[2][2*jq]);
                ah[3][2*jq]   = ffma2(xd3, wl, ah[3][2*jq]);
                ah[0][2*jq+1] = ffma2(xd0, wh, ah[0][2*jq+1]);
                ah[1][2*jq+1] = ffma2(xd1, wh, ah[1][2*jq+1]);
                ah[2][2*jq+1] = ffma2(xd2, wh, ah[2][2*jq+1]);
                ah[3][2*jq+1] = ffma2(xd3, wh, ah[3][2*jq+1]);
            }
        }
        // store relu(h) -> hs (separate buffer; no pre-sync needed)
        #pragma unroll
        for (int j = 0; j < 8; j++) {
            int ca = cA0 + 2*j, cb = ca + 1;
            float4 va = make_float4(fmaxf(ah[0][j].x,0.f), fmaxf(ah[1][j].x,0.f),
                                    fmaxf(ah[2][j].x,0.f), fmaxf(ah[3][j].x,0.f));
            float4 vb = make_float4(fmaxf(ah[0][j].y,0.f), fmaxf(ah[1][j].y,0.f),
                                    fmaxf(ah[2][j].y,0.f), fmaxf(ah[3][j].y,0.f));
            *(float4*)(hs + ca*64 + (r0 ^ SWR(ca))) = va;
            *(float4*)(hs + cb*64 + (r0 ^ SWR(cb))) = vb;
        }

        // residual: rc = x @ wr + (b2+br)  (cols c0..c0+7)
        float2 rc[4][4];
        #pragma unroll
        for (int i = 0; i < 4; i++)
            #pragma unroll
            for (int j = 0; j < 4; j++) rc[i][j] = by[j];
        #pragma unroll
        for (int k = 0; k < 16; k++) {
            float4 xv = *(const float4*)(xs1 + k*64 + r0);
            float2 xd0 = dupp(xv.x), xd1 = dupp(xv.y), xd2 = dupp(xv.z), xd3 = dupp(xv.w);
            float4 w0 = wrs[k*32 + f0], w1v = wrs[k*32 + f0 + 1];
            float2 al = lo2(w0), ah2 = hi2(w0), bl = lo2(w1v), bh2 = hi2(w1v);
            rc[0][0]=ffma2(xd0,al,rc[0][0]); rc[1][0]=ffma2(xd1,al,rc[1][0]);
            rc[2][0]=ffma2(xd2,al,rc[2][0]); rc[3][0]=ffma2(xd3,al,rc[3][0]);
            rc[0][1]=ffma2(xd0,ah2,rc[0][1]); rc[1][1]=ffma2(xd1,ah2,rc[1][1]);
            rc[2][1]=ffma2(xd2,ah2,rc[2][1]); rc[3][1]=ffma2(xd3,ah2,rc[3][1]);
            rc[0][2]=ffma2(xd0,bl,rc[0][2]); rc[1][2]=ffma2(xd1,bl,rc[1][2]);
            rc[2][2]=ffma2(xd2,bl,rc[2][2]); rc[3][2]=ffma2(xd3,bl,rc[3][2]);
            rc[0][3]=ffma2(xd0,bh2,rc[0][3]); rc[1][3]=ffma2(xd1,bh2,rc[1][3]);
            rc[2][3]=ffma2(xd2,bh2,rc[2][3]); rc[3][3]=ffma2(xd3,bh2,rc[3][3]);
        }
        __syncthreads();                       // hs visible to all

        // phase B: rc += h @ w2  (K=256)
        #pragma unroll 2
        for (int k = 0; k < 256; k++) {
            float4 xv = *(const float4*)(hs + k*64 + (r0 ^ SWR(k)));
            float2 xd0 = dupp(xv.x), xd1 = dupp(xv.y), xd2 = dupp(xv.z), xd3 = dupp(xv.w);
            float4 w0 = w2s[k*32 + f0], w1v = w2s[k*32 + f0 + 1];
            float2 al = lo2(w0), ah2 = hi2(w0), bl = lo2(w1v), bh2 = hi2(w1v);
            rc[0][0]=ffma2(xd0,al,rc[0][0]); rc[1][0]=ffma2(xd1,al,rc[1][0]);
            rc[2][0]=ffma2(xd2,al,rc[2][0]); rc[3][0]=ffma2(xd3,al,rc[3][0]);
            rc[0][1]=ffma2(xd0,ah2,rc[0][1]); rc[1][1]=ffma2(xd1,ah2,rc[1][1]);
            rc[2][1]=ffma2(xd2,ah2,rc[2][1]); rc[3][1]=ffma2(xd3,ah2,rc[3][1]);
            rc[0][2]=ffma2(xd0,bl,rc[0][2]); rc[1][2]=ffma2(xd1,bl,rc[1][2]);
            rc[2][2]=ffma2(xd2,bl,rc[2][2]); rc[3][2]=ffma2(xd3,bl,rc[3][2]);
            rc[0][3]=ffma2(xd0,bh2,rc[0][3]); rc[1][3]=ffma2(xd1,bh2,rc[1][3]);
            rc[2][3]=ffma2(xd2,bh2,rc[2][3]); rc[3][3]=ffma2(xd3,bh2,rc[3][3]);
        }

        // LN partials: reduce over 8 cols in-thread, then 4 cg lanes, then 4 warp_cols via smem
        float ps[4], pq[4];
        #pragma unroll
        for (int i = 0; i < 4; i++) {
            float s = 0.f, q = 0.f;
            #pragma unroll
            for (int j = 0; j < 4; j++) {
                s += rc[i][j].x + rc[i][j].y;
                q += rc[i][j].x*rc[i][j].x + rc[i][j].y*rc[i][j].y;
            }
            s += __shfl_xor_sync(0xffffffffu, s, 1);
            q += __shfl_xor_sync(0xffffffffu, q, 1);
            s += __shfl_xor_sync(0xffffffffu, s, 2);
            q += __shfl_xor_sync(0xffffffffu, q, 2);
            ps[i] = s; pq[i] = q;
        }
        if (cg == 0) {
            #pragma unroll
            for (int i = 0; i < 4; i++) part[(r0+i)*4 + wc] = make_float2(ps[i], pq[i]);
        }
        __syncthreads();
        float4 g0 = *(const float4*)(g  + c0), g1 = *(const float4*)(g  + c0 + 4);
        float4 e0 = *(const float4*)(be + c0), e1 = *(const float4*)(be + c0 + 4);
        #pragma unroll
        for (int i = 0; i < 4; i++) {
            int row = r0 + i;
            float4 p01 = *(const float4*)(part + row*4);
            float4 p23 = *(const float4*)(part + row*4 + 2);
            float s = p01.x + p01.z + p23.x + p23.z;
            float q = p01.y + p01.w + p23.y + p23.w;
            float mu = s*(1.f/128.f);
            float rs = rsqrtf(q*(1.f/128.f) - mu*mu + EPS_);
            float4 o0, o1;
            o0.x = (rc[i][0].x - mu)*rs*g0.x + e0.x;
            o0.y = (rc[i][0].y - mu)*rs*g0.y + e0.y;
            o0.z = (rc[i][1].x - mu)*rs*g0.z + e0.z;
            o0.w = (rc[i][1].y - mu)*rs*g0.w + e0.w;
            o1.x = (rc[i][2].x - mu)*rs*g1.x + e1.x;
            o1.y = (rc[i][2].y - mu)*rs*g1.y + e1.y;
            o1.z = (rc[i][3].x - mu)*rs*g1.z + e1.z;
            o1.w = (rc[i][3].y - mu)*rs*g1.w + e1.w;
            float* op = g_bufA + (size_t)(row0 + row)*D_ + c0;
            *(float4*)op       = o0;
            *(float4*)(op + 4) = o1;
        }
    }
}

// ============ K2: encoder LEMblock 128->128->128, 64-row tiles ============
// smem: w1s/wrs/w2s f4[128*32] natural, xs f[128*64], part f2[64*4]
#define SM2_BYTES (3*128*32*16 + 128*64*4 + 64*4*8)

__global__ __launch_bounds__(256, 1)
void k2_encoder(const float* __restrict__ ew1, const float* __restrict__ eb1,
                const float* __restrict__ ew2, const float* __restrict__ eb2,
                const float* __restrict__ ewr, const float* __restrict__ ebr,
                const float* __restrict__ eg,  const float* __restrict__ ebe,
                int layer)
{
    extern __shared__ unsigned char smraw[];
    float4* w1s = (float4*)smraw;              // [128][32]
    float4* wrs = w1s + 128*32;
    float4* w2s = wrs + 128*32;
    float*  xs  = (float*)(w2s + 128*32);      // [128][64]
    float2* part = (float2*)(xs + 128*64);     // [64][4]

    const float4* w1g = (const float4*)(ew1 + layer*D_*D_);
    const float4* wrg = (const float4*)(ewr + layer*D_*D_);
    const float4* w2g = (const float4*)(ew2 + layer*D_*D_);
    const float* zin  = layer ? g_bufB : g_bufA;
    float*       zout = layer ? g_bufA : g_bufB;

    int tid = threadIdx.x;
    for (int i = tid; i < 128*32; i += 256) {
        w1s[i] = w1g[i]; wrs[i] = wrg[i]; w2s[i] = w2g[i];
    }

    int wid = tid >> 5, lane = tid & 31;
    int wrow = wid & 1, wc = wid >> 1;         // 2 x 4 warp grid (32r x 32c tiles)
    int rg = lane >> 2, cg = lane & 3;
    int r0 = wrow*32 + rg*4;
    int c0 = wc*32 + cg*8;
    int f0 = wc*8 + cg*2;

    float2 bh[4], by[4];
    #pragma unroll
    for (int j = 0; j < 4; j++) {
        bh[j] = *(const float2*)(eb1 + layer*128 + c0 + 2*j);
        float2 a = *(const float2*)(eb2 + layer*128 + c0 + 2*j);
        float2 b = *(const float2*)(ebr + layer*128 + c0 + 2*j);
        by[j] = make_float2(a.x + b.x, a.y + b.y);
    }
    __syncthreads();

    const int NTILES = ROWS_/64;               // 5355
    for (int tile = blockIdx.x; tile < NTILES; tile += gridDim.x) {
        int row0 = tile*64;
        __syncthreads();                       // protect xs/part reuse
        {   // transpose-in: xs[c][r ^ SWR(c)]
            int r = tid >> 2, q0 = (tid & 3)*32;
            const float* src = zin + (size_t)(row0 + r)*D_ + q0;
            #pragma unroll
            for (int q4 = 0; q4 < 32; q4 += 4) {
                float4 v = *(const float4*)(src + q4);
                int c = q0 + q4;
                int rr = r ^ SWR(c);
                xs[(c+0)*64 + rr] = v.x;
                xs[(c+1)*64 + rr] = v.y;
                xs[(c+2)*64 + rr] = v.z;
                xs[(c+3)*64 + rr] = v.w;
            }
        }
        __syncthreads();

        // phase A (dual): ha = x@w1 + b1, rc = x@wr + bB
        float2 ha[4][4], rc[4][4];
        #pragma unroll
        for (int i = 0; i < 4; i++)
            #pragma unroll
            for (int j = 0; j < 4; j++) { ha[i][j] = bh[j]; rc[i][j] = by[j]; }
        #pragma unroll 2
        for (int k = 0; k < 128; k++) {
            float4 xv = *(const float4*)(xs + k*64 + (r0 ^ SWR(k)));
            float4 wa0 = w1s[k*32 + f0], wa1 = w1s[k*32 + f0 + 1];
            float4 wb0 = wrs[k*32 + f0], wb1 = wrs[k*32 + f0 + 1];
            float2 xd0 = dupp(xv.x), xd1 = dupp(xv.y), xd2 = dupp(xv.z), xd3 = dupp(xv.w);
            float2 a0 = lo2(wa0), a1 = hi2(wa0), a2 = lo2(wa1), a3 = hi2(wa1);
            float2 b0 = lo2(wb0), b1v = hi2(wb0), b2v = lo2(wb1), b3 = hi2(wb1);
            ha[0][0]=ffma2(xd0,a0,ha[0][0]); ha[1][0]=ffma2(xd1,a0,ha[1][0]);
            ha[2][0]=ffma2(xd2,a0,ha[2][0]); ha[3][0]=ffma2(xd3,a0,ha[3][0]);
            ha[0][1]=ffma2(xd0,a1,ha[0][1]); ha[1][1]=ffma2(xd1,a1,ha[1][1]);
            ha[2][1]=ffma2(xd2,a1,ha[2][1]); ha[3][1]=ffma2(xd3,a1,ha[3][1]);
            ha[0][2]=ffma2(xd0,a2,ha[0][2]); ha[1][2]=ffma2(xd1,a2,ha[1][2]);
            ha[2][2]=ffma2(xd2,a2,ha[2][2]); ha[3][2]=ffma2(xd3,a2,ha[3][2]);
            ha[0][3]=ffma2(xd0,a3,ha[0][3]); ha[1][3]=ffma2(xd1,a3,ha[1][3]);
            ha[2][3]=ffma2(xd2,a3,ha[2][3]); ha[3][3]=ffma2(xd3,a3,ha[3][3]);
            rc[0][0]=ffma2(xd0,b0,rc[0][0]); rc[1][0]=ffma2(xd1,b0,rc[1][0]);
            rc[2][0]=ffma2(xd2,b0,rc[2][0]); rc[3][0]=ffma2(xd3,b0,rc[3][0]);
            rc[0][1]=ffma2(xd0,b1v,rc[0][1]); rc[1][1]=ffma2(xd1,b1v,rc[1][1]);
            rc[2][1]=ffma2(xd2,b1v,rc[2][1]); rc[3][1]=ffma2(xd3,b1v,rc[3][1]);
            rc[0][2]=ffma2(xd0,b2v,rc[0][2]); rc[1][2]=ffma2(xd1,b2v,rc[1][2]);
            rc[2][2]=ffma2(xd2,b2v,rc[2][2]); rc[3][2]=ffma2(xd3,b2v,rc[3][2]);
            rc[0][3]=ffma2(xd0,b3,rc[0][3]); rc[1][3]=ffma2(xd1,b3,rc[1][3]);
            rc[2][3]=ffma2(xd2,b3,rc[2][3]); rc[3][3]=ffma2(xd3,b3,rc[3][3]);
        }
        __syncthreads();                       // all x reads done
        // store relu(h) over xs
        #pragma unroll
        for (int j = 0; j < 4; j++) {
            int ca = c0 + 2*j, cb = ca + 1;
            float4 va = make_float4(fmaxf(ha[0][j].x,0.f), fmaxf(ha[1][j].x,0.f),
                                    fmaxf(ha[2][j].x,0.f), fmaxf(ha[3][j].x,0.f));
            float4 vb = make_float4(fmaxf(ha[0][j].y,0.f), fmaxf(ha[1][j].y,0.f),
                                    fmaxf(ha[2][j].y,0.f), fmaxf(ha[3][j].y,0.f));
            *(float4*)(xs + ca*64 + (r0 ^ SWR(ca))) = va;
            *(float4*)(xs + cb*64 + (r0 ^ SWR(cb))) = vb;
        }
        __syncthreads();

        // phase B: rc += h @ w2
        #pragma unroll 2
        for (int k = 0; k < 128; k++) {
            float4 xv = *(const float4*)(xs + k*64 + (r0 ^ SWR(k)));
            float4 w0 = w2s[k*32 + f0], w1v = w2s[k*32 + f0 + 1];
            float2 xd0 = dupp(xv.x), xd1 = dupp(xv.y), xd2 = dupp(xv.z), xd3 = dupp(xv.w);
            float2 a0 = lo2(w0), a1 = hi2(w0), a2 = lo2(w1v), a3 = hi2(w1v);
            rc[0][0]=ffma2(xd0,a0,rc[0][0]); rc[1][0]=ffma2(xd1,a0,rc[1][0]);
            rc[2][0]=ffma2(xd2,a0,rc[2][0]); rc[3][0]=ffma2(xd3,a0,rc[3][0]);
            rc[0][1]=ffma2(xd0,a1,rc[0][1]); rc[1][1]=ffma2(xd1,a1,rc[1][1]);
            rc[2][1]=ffma2(xd2,a1,rc[2][1]); rc[3][1]=ffma2(xd3,a1,rc[3][1]);
            rc[0][2]=ffma2(xd0,a2,rc[0][2]); rc[1][2]=ffma2(xd1,a2,rc[1][2]);
            rc[2][2]=ffma2(xd2,a2,rc[2][2]); rc[3][2]=ffma2(xd3,a2,rc[3][2]);
            rc[0][3]=ffma2(xd0,a3,rc[0][3]); rc[1][3]=ffma2(xd1,a3,rc[1][3]);
            rc[2][3]=ffma2(xd2,a3,rc[2][3]); rc[3][3]=ffma2(xd3,a3,rc[3][3]);
        }

        // LN partials
        float ps[4], pq[4];
        #pragma unroll
        for (int i = 0; i < 4; i++) {
            float s = 0.f, q = 0.f;
            #pragma unroll
            for (int j = 0; j < 4; j++) {
                s += rc[i][j].x + rc[i][j].y;
                q += rc[i][j].x*rc[i][j].x + rc[i][j].y*rc[i][j].y;
            }
            s += __shfl_xor_sync(0xffffffffu, s, 1);
            q += __shfl_xor_sync(0xffffffffu, q, 1);
            s += __shfl_xor_sync(0xffffffffu, s, 2);
            q += __shfl_xor_sync(0xffffffffu, q, 2);
            ps[i] = s; pq[i] = q;
        }
        if (cg == 0) {
            #pragma unroll
            for (int i = 0; i < 4; i++) part[(r0+i)*4 + wc] = make_float2(ps[i], pq[i]);
        }
        __syncthreads();
        float4 g0 = *(const float4*)(eg + layer*128 + c0);
        float4 g1 = *(const float4*)(eg + layer*128 + c0 + 4);
        float4 e0 = *(const float4*)(ebe + layer*128 + c0);
        float4 e1 = *(const float4*)(ebe + layer*128 + c0 + 4);
        #pragma unroll
        for (int i = 0; i < 4; i++) {
            int row = r0 + i;
            float4 p01 = *(const float4*)(part + row*4);
            float4 p23 = *(const float4*)(part + row*4 + 2);
            float s = p01.x + p01.z + p23.x + p23.z;
            float q = p01.y + p01.w + p23.y + p23.w;
            float mu = s*(1.f/128.f);
            float rs = rsqrtf(q*(1.f/128.f) - mu*mu + EPS_);
            float4 o0, o1;
            o0.x = (rc[i][0].x - mu)*rs*g0.x + e0.x;
            o0.y = (rc[i][0].y - mu)*rs*g0.y + e0.y;
            o0.z = (rc[i][1].x - mu)*rs*g0.z + e0.z;
            o0.w = (rc[i][1].y - mu)*rs*g0.w + e0.w;
            o1.x = (rc[i][2].x - mu)*rs*g1.x + e1.x;
            o1.y = (rc[i][2].y - mu)*rs*g1.y + e1.y;
            o1.z = (rc[i][3].x - mu)*rs*g1.z + e1.z;
            o1.w = (rc[i][3].y - mu)*rs*g1.w + e1.w;
            float* op = zout + (size_t)(row0 + row)*D_ + c0;
            *(float4*)op       = o0;
            *(float4*)(op + 4) = o1;
        }
    }
}

// ============ K4: EMA recurrence + SiLU + transpose (unchanged) ============
__global__ void k4_ema(const float* __restrict__ omega)
{
    __shared__ float tile[128*65];
    int bn = blockIdx.x, d = threadIdx.x;
    float q0 = g_ema[d*4+0], a0 = g_ema[d*4+1];
    float q1 = g_ema[d*4+2], a1 = g_ema[d*4+3];
    float om = omega[d];
    const float* src = g_bufA + (size_t)bn*PNUM_*D_ + d;
    float* dst = g_u + (size_t)bn*KHEAD_;
    float s0 = 0.f, s1 = 0.f;
    for (int chunk = 0; chunk < 4; chunk++) {
        int tbase = chunk*64;
        int tn = (PNUM_ - tbase < 64) ? (PNUM_ - tbase) : 64;
        #pragma unroll 4
        for (int i = 0; i < tn; i++) {
            float xv = src[(size_t)(tbase + i)*D_];
            s0 = fmaf(s0, q0, xv);
            s1 = fmaf(s1, q1, xv);
            float v = fmaf(om, xv, fmaf(a0, s0, a1*s1));
            tile[d*65 + i] = v * (1.f/(1.f + __expf(-v)));
        }
        __syncthreads();
        for (int i = d; i < 128*64; i += 128) {
            int dd = i >> 6, tt = i & 63;
            if (tt < tn) dst[dd*PNUM_ + tbase + tt] = tile[dd*65 + tt];
        }
        __syncthreads();
    }
}

// ============ K5: head GEMM (unchanged from R6) ============
__global__ void k5_init(const float* __restrict__ hb, float* __restrict__ out)
{
    int i = blockIdx.x*blockDim.x + threadIdx.x;
    if (i < BN_*PRED_) out[i] = hb[i % PRED_];
}

__global__ __launch_bounds__(192, 1)
void k5_head(const float* __restrict__ hw, float* __restrict__ out)
{
    __shared__ float u2[64*64];
    __shared__ float2 ws2[64*48];
    int tid = threadIdx.x;
    int cg = tid % 24, rg = tid / 24;
    int c0 = cg*4, r0 = rg*8;
    int row0 = blockIdx.x * 64;
    int k0base = blockIdx.y * 3264;

    float2 acc[8][2];
    #pragma unroll
    for (int i = 0; i < 8; i++) { acc[i][0] = make_float2(0.f,0.f); acc[i][1] = make_float2(0.f,0.f); }

    for (int ch = 0; ch < 51; ch++) {
        int k0 = k0base + ch*64;
        __syncthreads();
        for (int idx = tid; idx < 64*16; idx += 192) {
            int r = idx >> 4, q = (idx & 15)*4;
            float4 v = *(const float4*)(g_u + (size_t)(row0 + r)*KHEAD_ + k0 + q);
            int rr = r ^ SWR(q);
            u2[(q+0)*64 + rr] = v.x;
            u2[(q+1)*64 + rr] = v.y;
            u2[(q+2)*64 + rr] = v.z;
            u2[(q+3)*64 + rr] = v.w;
        }
        for (int idx = tid; idx < 64*48; idx += 192) {
            int k = idx / 48, s = idx - k*48;
            int cp = (s % 24)*2 + s/24;
            ws2[idx] = *(const float2*)(hw + (size_t)(k0 + k)*96 + 2*cp);
        }
        __syncthreads();
        #pragma unroll 2
        for (int kk = 0; kk < 64; kk++) {
            int rx = r0 ^ SWR(kk);
            float4 xa = *(const float4*)(u2 + kk*64 + rx);
            float4 xb = *(const float4*)(u2 + kk*64 + rx + 4);
            float2 w0 = ws2[kk*48 + cg];
            float2 w1v = ws2[kk*48 + 24 + cg];
            float2 xd[8] = {dup2(xa.x),dup2(xa.y),dup2(xa.z),dup2(xa.w),
                            dup2(xb.x),dup2(xb.y),dup2(xb.z),dup2(xb.w)};
            #pragma unroll
            for (int i = 0; i < 8; i++) {
                acc[i][0] = ffma2(xd[i], w0,  acc[i][0]);
                acc[i][1] = ffma2(xd[i], w1v, acc[i][1]);
            }
        }
    }
    #pragma unroll
    for (int i = 0; i < 8; i++) {
        float* op = out + (size_t)(row0 + r0 + i)*PRED_ + c0;
        atomicAdd(op+0, acc[i][0].x);
        atomicAdd(op+1, acc[i][0].y);
        atomicAdd(op+2, acc[i][1].x);
        atomicAdd(op+3, acc[i][1].y);
    }
}

// ============ launch ============
extern "C" void kernel_launch(void* const* d_in, const int* in_sizes, int n_in,
                              void* d_out, int out_size)
{
    const float* x       = (const float*)d_in[0];
    const float* fp_w1   = (const float*)d_in[1];
    const float* fp_b1   = (const float*)d_in[2];
    const float* fp_w2   = (const float*)d_in[3];
    const float* fp_b2   = (const float*)d_in[4];
    const float* fp_wr   = (const float*)d_in[5];
    const float* fp_br   = (const float*)d_in[6];
    const float* fp_g    = (const float*)d_in[7];
    const float* fp_be   = (const float*)d_in[8];
    const float* enc_w1  = (const float*)d_in[9];
    const float* enc_b1  = (const float*)d_in[10];
    const float* enc_w2  = (const float*)d_in[11];
    const float* enc_b2  = (const float*)d_in[12];
    const float* enc_wr  = (const float*)d_in[13];
    const float* enc_br  = (const float*)d_in[14];
    const float* enc_g   = (const float*)d_in[15];
    const float* enc_be  = (const float*)d_in[16];
    const float* e_delta = (const float*)d_in[17];
    const float* e_alpha = (const float*)d_in[18];
    const float* e_beta  = (const float*)d_in[19];
    const float* e_gamma = (const float*)d_in[20];
    const float* e_omega = (const float*)d_in[21];
    const float* head_w  = (const float*)d_in[22];
    const float* head_b  = (const float*)d_in[23];
    float* out = (float*)d_out;

    cudaFuncSetAttribute(k1_featproj, cudaFuncAttributeMaxDynamicSharedMemorySize, SM1_BYTES);
    cudaFuncSetAttribute(k2_encoder,  cudaFuncAttributeMaxDynamicSharedMemorySize, SM2_BYTES);

    k0_emaparam<<<1, 128>>>(e_delta, e_alpha, e_beta, e_gamma);
    k1_featproj<<<148, 256, SM1_BYTES>>>(x, fp_w1, fp_b1, fp_w2, fp_b2, fp_wr, fp_br, fp_g, fp_be);
    k2_encoder<<<148, 256, SM2_BYTES>>>(enc_w1, enc_b1, enc_w2, enc_b2, enc_wr, enc_br, enc_g, enc_be, 0);
    k2_encoder<<<148, 256, SM2_BYTES>>>(enc_w1, enc_b1, enc_w2, enc_b2, enc_wr, enc_br, enc_g, enc_be, 1);
    k4_ema<<<BN_, 128>>>(e_omega);
    k5_init<<<(BN_*PRED_ + 255)/256, 256>>>(head_b, out);
    k5_head<<<dim3(21, 10), 192>>>(head_w, out);
}